// round 10
// baseline (speedup 1.0000x reference)
#include <cuda_runtime.h>
#include <cuda_fp16.h>
#include <math.h>
#include <stdint.h>

// ===========================================================================
// KnotAttention via mma.sync m16n8k16 fp16 + ldmatrix. NT=64 tiles, 2 CTAs/SM,
// DOUBLE-buffered A and W cp.async pipelines (1-iteration prefetch distance).
//  E: per tile: Q=A0@Wq; per r: K_r=A_r@Wk_r; E=exp(QK/sqrt32); partials
//  R: reduce partials -> 1/denominator (softmax over NODE axis)
//  O: per r: V_r=A_r@Wv_r; acc += (E*Sinv)*V_r; write out
// ===========================================================================

#define NT       64
#define THREADS  256
#define MAXN     131072
#define MAXTILES (MAXN / NT)
#define SCALE    0.17677669529663687f   // 1/sqrt(32)
#define SH       136                    // smem row stride in halves (272B)
#define ROWB     272
#define A_HALVES (NT * SH)              // 8704
#define W_HALVES (128 * SH)             // 17408
#define SMEM_SZ  ((2 * A_HALVES + 2 * W_HALVES) * 2)   // 104448 B -> 2 CTAs/SM
#define AS_T     132                    // fp32 transpose stride (O epilogue)

__device__ float  g_E[(size_t)20 * MAXN];
__device__ float  g_part[20 * MAXTILES];
__device__ float  g_Sinv[20];
__device__ int    g_is64;
__device__ __half g_Wh[11 * 128 * 128];          // [slot][n][k]
__device__ __half g_xh[(size_t)MAXN * 128];      // [n][k]

// -------- helpers --------
__device__ __forceinline__ uint32_t smem_u32(const void* p) {
    uint32_t a;
    asm("{ .reg .u64 t; cvta.to.shared.u64 t, %1; cvt.u32.u64 %0, t; }" : "=r"(a) : "l"(p));
    return a;
}
__device__ __forceinline__ void cpa16(uint32_t s, const void* g) {
    asm volatile("cp.async.cg.shared.global [%0], [%1], 16;" :: "r"(s), "l"(g) : "memory");
}
__device__ __forceinline__ void cpa_commit() { asm volatile("cp.async.commit_group;" ::: "memory"); }
__device__ __forceinline__ void cpa_wait1()  { asm volatile("cp.async.wait_group 1;" ::: "memory"); }
__device__ __forceinline__ void cpa_wait0()  { asm volatile("cp.async.wait_group 0;" ::: "memory"); }

__device__ __forceinline__ void ldsm4(uint32_t& r0, uint32_t& r1, uint32_t& r2,
                                      uint32_t& r3, uint32_t addr) {
    asm volatile("ldmatrix.sync.aligned.m8n8.x4.shared.b16 {%0,%1,%2,%3}, [%4];"
                 : "=r"(r0), "=r"(r1), "=r"(r2), "=r"(r3) : "r"(addr));
}
__device__ __forceinline__ void mma16816(float* c, uint32_t a0, uint32_t a1,
                                         uint32_t a2, uint32_t a3,
                                         uint32_t b0, uint32_t b1) {
    asm volatile(
        "mma.sync.aligned.m16n8k16.row.col.f32.f16.f16.f32 "
        "{%0,%1,%2,%3}, {%4,%5,%6,%7}, {%8,%9}, {%0,%1,%2,%3};"
        : "+f"(c[0]), "+f"(c[1]), "+f"(c[2]), "+f"(c[3])
        : "r"(a0), "r"(a1), "r"(a2), "r"(a3), "r"(b0), "r"(b1));
}

// -------- prep kernels --------
__global__ void knot_prep_x(const float* __restrict__ x, int total)
{
    for (int i = blockIdx.x * 256 + threadIdx.x; i < total; i += gridDim.x * 256)
        g_xh[i] = __float2half_rn(x[i]);
}
__global__ void knot_prep_w(const float* __restrict__ wq, const float* __restrict__ wk,
                            const float* __restrict__ wv)
{
    int slot = blockIdx.x;
    __half* dst = g_Wh + slot * 16384;
    for (int i = 0; i < 64; ++i) {
        int f = threadIdx.x + 256 * i;
        int n = f >> 7, d = f & 127;
        int h = n >> 5, k = n & 31;
        float v;
        if (slot == 0)      v = wq[((size_t)h * 128 + d) * 32 + k];
        else if (slot <= 5) v = wk[(((size_t)(h * 5 + (slot - 1)) * 128) + d) * 32 + k];
        else                v = wv[(((size_t)(h * 5 + (slot - 6)) * 128) + d) * 32 + k];
        dst[n * 128 + d] = __float2half_rn(v);
    }
}
__global__ void knot_detect(const int* __restrict__ nbr_i32)
{
    if (threadIdx.x == 0 && blockIdx.x == 0) {
        int any = 0;
        #pragma unroll
        for (int i = 1; i < 64; i += 2) any |= nbr_i32[i];
        g_is64 = (any == 0) ? 1 : 0;
    }
}

// -------- staging (cp.async 16B) --------
__device__ __forceinline__ void stage_A(__half* sA, const void* __restrict__ nbr,
                                        int is64, int n0, int r, int N)
{
    int t = threadIdx.x;
    #pragma unroll
    for (int i = 0; i < 4; ++i) {
        int f = t + 256 * i;               // 64 rows x 16 chunks of 16B
        int row = f >> 4, c16 = f & 15;
        int n = n0 + row;
        int nc = (n < N) ? n : 0;
        long long src;
        if (r == 0) src = nc;
        else {
            long long e = (long long)nc * 4 + (r - 1);
            src = is64 ? __ldg((const long long*)nbr + e)
                       : (long long)__ldg((const int*)nbr + e);
        }
        if (src < 0) src = 0;
        if (src >= N) src = N - 1;
        cpa16(smem_u32(sA + row * SH + c16 * 8), g_xh + ((size_t)src << 7) + c16 * 8);
    }
}
__device__ __forceinline__ void stage_W(__half* sW, int slot)
{
    const __half* src = g_Wh + slot * 16384;
    int t = threadIdx.x;
    #pragma unroll
    for (int i = 0; i < 8; ++i) {
        int f = t + 256 * i;
        int row = f >> 4, c16 = f & 15;
        cpa16(smem_u32(sW + row * SH + c16 * 8), src + row * 128 + c16 * 8);
    }
}

// -------- warp GEMM via ldmatrix: 32(m) x 32(n) per warp --------
__device__ __forceinline__ void gemm64m(uint32_t aAddr, uint32_t bAddr,
                                        float C[2][4][4])
{
    #pragma unroll
    for (int ks = 0; ks < 8; ++ks) {
        uint32_t a0[4], a1[4], b0[4], b1[4];
        ldsm4(a0[0], a0[1], a0[2], a0[3], aAddr + ks * 32);
        ldsm4(a1[0], a1[1], a1[2], a1[3], aAddr + 16 * ROWB + ks * 32);
        ldsm4(b0[0], b0[1], b0[2], b0[3], bAddr + ks * 32);
        ldsm4(b1[0], b1[1], b1[2], b1[3], bAddr + 16 * ROWB + ks * 32);
        mma16816(C[0][0], a0[0], a0[1], a0[2], a0[3], b0[0], b0[1]);
        mma16816(C[0][1], a0[0], a0[1], a0[2], a0[3], b0[2], b0[3]);
        mma16816(C[0][2], a0[0], a0[1], a0[2], a0[3], b1[0], b1[1]);
        mma16816(C[0][3], a0[0], a0[1], a0[2], a0[3], b1[2], b1[3]);
        mma16816(C[1][0], a1[0], a1[1], a1[2], a1[3], b0[0], b0[1]);
        mma16816(C[1][1], a1[0], a1[1], a1[2], a1[3], b0[2], b0[3]);
        mma16816(C[1][2], a1[0], a1[1], a1[2], a1[3], b1[0], b1[1]);
        mma16816(C[1][3], a1[0], a1[1], a1[2], a1[3], b1[2], b1[3]);
    }
}

#define ZERO_C(C)                                                   \
    _Pragma("unroll") for (int mt = 0; mt < 2; ++mt)                \
    _Pragma("unroll") for (int nt = 0; nt < 4; ++nt)                \
    _Pragma("unroll") for (int ci = 0; ci < 4; ++ci) C[mt][nt][ci] = 0.f;

// -------- kernel E --------
// GEMMs i=0..5: i=0 Q=(A0,W0); i=r+1 K_r=(A_r, W_{r+1}).
// A bufs: abuf0={A0,A2,A4}, abuf1={A1,A3}. W bufs: parity of slot.
__global__ __launch_bounds__(THREADS, 2)
void knot_E(const void* __restrict__ nbr, int N)
{
    extern __shared__ __align__(16) char smc[];
    __half* sA0 = (__half*)smc;
    __half* sA1 = sA0 + A_HALVES;
    __half* sW0 = sA1 + A_HALVES;
    __half* sW1 = sW0 + W_HALVES;
    __half* sAb[2] = { sA0, sA1 };
    __half* sWb[2] = { sW0, sW1 };
    __shared__ float warr[8];

    const int t = threadIdx.x, w = t >> 5, l = t & 31;
    const int wm = w >> 2, wn = w & 3, g = l >> 2, t4 = l & 3;
    const int tile = blockIdx.x, n0 = tile * NT;
    const int is64 = g_is64;
    const int h = wn;

    const int j = l >> 3, lr = l & 7;
    const uint32_t aOff = (wm * 32 + (j & 1) * 8 + lr) * ROWB + (j >> 1) * 16;
    const uint32_t bOff = (wn * 32 + (j >> 1) * 8 + lr) * ROWB + (j & 1) * 16;
    const uint32_t aAb[2] = { smem_u32(sA0) + aOff, smem_u32(sA1) + aOff };
    const uint32_t bAb[2] = { smem_u32(sW0) + bOff, smem_u32(sW1) + bOff };

    // prologue: g1={W0,A0}, g2={W1,A1}
    stage_W(sW0, 0); stage_A(sA0, nbr, is64, n0, 0, N); cpa_commit();
    stage_W(sW1, 1); stage_A(sA1, nbr, is64, n0, 1, N); cpa_commit();

    // ---- i=0: Q = (abuf0, wbuf0) ----
    float qC[2][4][4]; ZERO_C(qC);
    cpa_wait1();
    __syncthreads();
    gemm64m(aAb[0], bAb[0], qC);
    __syncthreads();                      // wbuf0 reads done
    stage_W(sW0, 2); cpa_commit();        // g3 = {W2}

    // ---- r=0..4: K_r = (abuf[r&1], wbuf[(r+1)&1]) ----
    for (int r = 0; r < 5; ++r) {
        if (r < 4) cpa_wait1(); else cpa_wait0();
        __syncthreads();

        float kC[2][4][4]; ZERO_C(kC);
        gemm64m(aAb[r & 1], bAb[(r + 1) & 1], kC);

        // ---- logits, exp, E store, partial sums (head h = wn) ----
        float hs = 0.f;
        #pragma unroll
        for (int mt = 0; mt < 2; ++mt) {
            #pragma unroll
            for (int rr2 = 0; rr2 < 2; ++rr2) {
                int n = n0 + wm * 32 + mt * 16 + g + rr2 * 8;
                float ds = 0.f;
                #pragma unroll
                for (int nt = 0; nt < 4; ++nt) {
                    ds = fmaf(qC[mt][nt][rr2 * 2],     kC[mt][nt][rr2 * 2],     ds);
                    ds = fmaf(qC[mt][nt][rr2 * 2 + 1], kC[mt][nt][rr2 * 2 + 1], ds);
                }
                ds += __shfl_xor_sync(0xFFFFFFFFu, ds, 1);
                ds += __shfl_xor_sync(0xFFFFFFFFu, ds, 2);
                if (t4 == 0) {
                    float e = 0.f;
                    if (n < N) {
                        e = __expf(ds * SCALE);
                        g_E[(size_t)(h * 5 + r) * N + n] = e;
                    }
                    hs += e;
                }
            }
        }
        #pragma unroll
        for (int o = 16; o > 0; o >>= 1)
            hs += __shfl_down_sync(0xFFFFFFFFu, hs, o);
        if (l == 0) warr[w] = hs;
        __syncthreads();                  // warr visible + all smem reads done
        if (t < 4)
            g_part[(t * 5 + r) * MAXTILES + tile] = warr[t] + warr[4 + t];

        // stage for GEMM i+2 = r+3: A_{r+2} -> abuf[r&1], W_{r+3} -> wbuf[(r+1)&1]
        bool st = false;
        if (r + 2 <= 4) { stage_A(sAb[r & 1], nbr, is64, n0, r + 2, N); st = true; }
        if (r + 3 <= 5) { stage_W(sWb[(r + 1) & 1], r + 3); st = true; }
        if (st) cpa_commit();
    }
}

// -------- kernel R --------
__global__ void knot_R(int cnt)
{
    __shared__ float smr[256];
    const int b = blockIdx.x;
    float s = 0.f;
    for (int i = threadIdx.x; i < cnt; i += 256) s += g_part[b * MAXTILES + i];
    smr[threadIdx.x] = s;
    __syncthreads();
    for (int off = 128; off > 0; off >>= 1) {
        if (threadIdx.x < off) smr[threadIdx.x] += smr[threadIdx.x + off];
        __syncthreads();
    }
    if (threadIdx.x == 0) g_Sinv[b] = 1.0f / smr[0];
}

// -------- kernel O --------
// GEMMs r=0..4: V_r = (abuf[r&1], wbuf[r&1]), W slot 6+r.
__global__ __launch_bounds__(THREADS, 2)
void knot_O(const void* __restrict__ nbr, float* __restrict__ out, int N)
{
    extern __shared__ __align__(16) char smc[];
    __half* sA0 = (__half*)smc;
    __half* sA1 = sA0 + A_HALVES;
    __half* sW0 = sA1 + A_HALVES;
    __half* sW1 = sW0 + W_HALVES;
    __half* sAb[2] = { sA0, sA1 };
    __half* sWb[2] = { sW0, sW1 };

    const int t = threadIdx.x, w = t >> 5, l = t & 31;
    const int wm = w >> 2, wn = w & 3, g = l >> 2, t4 = l & 3;
    const int tile = blockIdx.x, n0 = tile * NT;
    const int is64 = g_is64;
    const int h = wn;

    const int j = l >> 3, lr = l & 7;
    const uint32_t aOff = (wm * 32 + (j & 1) * 8 + lr) * ROWB + (j >> 1) * 16;
    const uint32_t bOff = (wn * 32 + (j >> 1) * 8 + lr) * ROWB + (j & 1) * 16;
    const uint32_t aAb[2] = { smem_u32(sA0) + aOff, smem_u32(sA1) + aOff };
    const uint32_t bAb[2] = { smem_u32(sW0) + bOff, smem_u32(sW1) + bOff };

    // prologue: g1={A0,W6}, g2={A1,W7}
    stage_A(sA0, nbr, is64, n0, 0, N); stage_W(sW0, 6); cpa_commit();
    stage_A(sA1, nbr, is64, n0, 1, N); stage_W(sW1, 7); cpa_commit();

    float acc[2][4][4]; ZERO_C(acc);

    for (int r = 0; r < 5; ++r) {
        if (r < 4) cpa_wait1(); else cpa_wait0();
        __syncthreads();

        float C[2][4][4]; ZERO_C(C);
        gemm64m(aAb[r & 1], bAb[r & 1], C);

        float av[2][2];
        const float si = g_Sinv[h * 5 + r];
        #pragma unroll
        for (int mt = 0; mt < 2; ++mt)
            #pragma unroll
            for (int rr2 = 0; rr2 < 2; ++rr2) {
                int n = n0 + wm * 32 + mt * 16 + g + rr2 * 8;
                av[mt][rr2] = (n < N)
                    ? __ldg(&g_E[(size_t)(h * 5 + r) * N + n]) * si : 0.f;
            }
        #pragma unroll
        for (int mt = 0; mt < 2; ++mt)
            #pragma unroll
            for (int nt = 0; nt < 4; ++nt)
                #pragma unroll
                for (int ci = 0; ci < 4; ++ci)
                    acc[mt][nt][ci] = fmaf(av[mt][ci >> 1], C[mt][nt][ci],
                                           acc[mt][nt][ci]);
        __syncthreads();                  // smem reads of this iter done

        // stage for r+2: A_{r+2} -> abuf[r&1], W_{6+r+2} -> wbuf[r&1]
        if (r + 2 <= 4) {
            stage_A(sAb[r & 1], nbr, is64, n0, r + 2, N);
            stage_W(sWb[r & 1], 6 + r + 2);
            cpa_commit();
        }
    }

    // ---- transpose via smem (fp32 view), coalesced output ----
    float* sT = (float*)smc;              // 64 x AS_T floats = 33.8KB
    #pragma unroll
    for (int mt = 0; mt < 2; ++mt)
        #pragma unroll
        for (int nt = 0; nt < 4; ++nt)
            #pragma unroll
            for (int ci = 0; ci < 4; ++ci) {
                int row = wm * 32 + mt * 16 + g + (ci >> 1) * 8;
                int col = wn * 32 + nt * 8 + t4 * 2 + (ci & 1);
                sT[row * AS_T + col] = acc[mt][nt][ci];
            }
    __syncthreads();
    #pragma unroll
    for (int i = 0; i < 8; ++i) {
        int f = t + 256 * i;
        int row = f >> 5, c4 = f & 31;
        int n = n0 + row;
        if (n < N)
            *(float4*)(out + (size_t)n * 128 + c4 * 4) =
                *(const float4*)(sT + row * AS_T + c4 * 4);
    }
}

extern "C" void kernel_launch(void* const* d_in, const int* in_sizes, int n_in,
                              void* d_out, int out_size)
{
    const float* x   = (const float*)d_in[0];
    const void*  nbr = d_in[1];
    const float* wq  = (const float*)d_in[2];
    const float* wk  = (const float*)d_in[3];
    const float* wv  = (const float*)d_in[4];
    float*       out = (float*)d_out;

    const int N   = in_sizes[0] / 128;
    const int NBT = (N + NT - 1) / NT;

    cudaFuncSetAttribute(knot_E, cudaFuncAttributeMaxDynamicSharedMemorySize, SMEM_SZ);
    cudaFuncSetAttribute(knot_O, cudaFuncAttributeMaxDynamicSharedMemorySize, SMEM_SZ);

    knot_detect<<<1, 32>>>((const int*)nbr);
    knot_prep_x<<<1024, 256>>>(x, N * 128);
    knot_prep_w<<<11, 256>>>(wq, wk, wv);
    knot_E<<<NBT, THREADS, SMEM_SZ>>>(nbr, N);
    knot_R<<<20, 256>>>(NBT);
    knot_O<<<NBT, THREADS, SMEM_SZ>>>(nbr, out, N);
}